// round 7
// baseline (speedup 1.0000x reference)
#include <cuda_runtime.h>
#include <cstdint>

// ---------------------------------------------------------------------------
// FullGapModel collapse:
//   out[s] = sum_{i: row_seg[i]==s} (x_i^T Q x_i) / ||x_i||^2
//   Q[a,b] = sum_j weights[col_seg[j]] * SP[j,a] * SP[j,b]   (400x400, symmetric)
//
// Inputs (metadata order):
//   0: power_spectrum  f32 [N=100000, D=400]
//   1: support_points  f32 [M=2000,  D=400]
//   2: weights         f32 [1, T=100]
//   3: all_species     i32 [N]          (unused by reference)
//   4: row_seg         i32 [N]          (values in [0, S))
//   5: col_seg         i32 [M]          (values in [0, T))
// Output: f32 [S=2000]
// ---------------------------------------------------------------------------

#define D_DIM   400
#define QSTRIDE 448          // padded row stride; pad columns are zero
#define NBB     7            // float2 chunks per lane: b = 2*lane + 64*bb covers 448

// Scratch for Q (device global — no allocation allowed). 400*448*4 = 716.8 KB.
__device__ float g_Qp[D_DIM * QSTRIDE];

union F2U { float2 f; unsigned long long u; };

// Packed dual-fp32 FMA (sm_103a f32x2 pipe: 2x scalar FFMA throughput).
__device__ __forceinline__ unsigned long long fma2(unsigned long long a,
                                                   unsigned long long b,
                                                   unsigned long long c) {
    unsigned long long d;
    asm("fma.rn.f32x2 %0, %1, %2, %3;" : "=l"(d) : "l"(a), "l"(b), "l"(c));
    return d;
}

__device__ __forceinline__ float warp_sum(float v) {
    #pragma unroll
    for (int o = 16; o > 0; o >>= 1) v += __shfl_xor_sync(0xFFFFFFFFu, v, o);
    return v;
}

// ---------------------------------------------------------------------------
// Zero the output (harness poisons d_out with 0xAA).
// ---------------------------------------------------------------------------
__global__ void zero_out_kernel(float* __restrict__ out, int n) {
    int i = blockIdx.x * blockDim.x + threadIdx.x;
    if (i < n) out[i] = 0.0f;
}

// ---------------------------------------------------------------------------
// Build Q = SP^T * diag(w') * SP, where w'_j = weights[col_seg[j]].
// 32x32 output tile per 256-thread block, 2x2 register blocking per thread.
// Pad columns [400,448) are written as zeros (Bs loads are zero there).
// ---------------------------------------------------------------------------
__global__ __launch_bounds__(256)
void build_q_kernel(const float* __restrict__ SP,
                    const float* __restrict__ W,
                    const int*  __restrict__ colseg,
                    int M) {
    __shared__ float As[32][33];
    __shared__ float Bs[32][33];

    const int a0 = blockIdx.y * 32;       // row tile (a < 400)
    const int b0 = blockIdx.x * 32;       // col tile (b < 448, incl. pad)
    const int tid = threadIdx.x;
    const int ty = tid >> 4;              // 0..15
    const int tx = tid & 15;              // 0..15

    float c00 = 0.f, c01 = 0.f, c10 = 0.f, c11 = 0.f;

    for (int j0 = 0; j0 < M; j0 += 32) {
        // Cooperative load: 1024 elements per array, 4 per thread.
        #pragma unroll
        for (int e = tid; e < 1024; e += 256) {
            int jj  = e >> 5;
            int col = e & 31;
            int j   = j0 + jj;
            float av = 0.f, bv = 0.f;
            if (j < M) {
                float wp = W[colseg[j]];
                int a = a0 + col;
                int b = b0 + col;
                if (a < D_DIM) av = SP[(size_t)j * D_DIM + a] * wp;
                if (b < D_DIM) bv = SP[(size_t)j * D_DIM + b];
            }
            As[jj][col] = av;
            Bs[jj][col] = bv;
        }
        __syncthreads();

        #pragma unroll
        for (int jj = 0; jj < 32; ++jj) {
            float a0r = As[jj][ty];
            float a1r = As[jj][ty + 16];
            float b0r = Bs[jj][tx];
            float b1r = Bs[jj][tx + 16];
            c00 = fmaf(a0r, b0r, c00);
            c01 = fmaf(a0r, b1r, c01);
            c10 = fmaf(a1r, b0r, c10);
            c11 = fmaf(a1r, b1r, c11);
        }
        __syncthreads();
    }

    int a_lo = a0 + ty, a_hi = a0 + ty + 16;
    int b_lo = b0 + tx, b_hi = b0 + tx + 16;
    if (a_lo < D_DIM) {
        if (b_lo < QSTRIDE) g_Qp[(size_t)a_lo * QSTRIDE + b_lo] = c00;
        if (b_hi < QSTRIDE) g_Qp[(size_t)a_lo * QSTRIDE + b_hi] = c01;
    }
    if (a_hi < D_DIM) {
        if (b_lo < QSTRIDE) g_Qp[(size_t)a_hi * QSTRIDE + b_lo] = c10;
        if (b_hi < QSTRIDE) g_Qp[(size_t)a_hi * QSTRIDE + b_hi] = c11;
    }
}

// ---------------------------------------------------------------------------
// Main pass: per row i, v_i = (x^T Q x)/||x||^2; atomicAdd into out[row_seg[i]].
// 128 threads = 4 warps/block, 4 rows/warp, 16 rows/block.
// Per-lane x slices in registers (b = 2*lane + 64*bb), Q rows streamed,
// x_a broadcast via uniform-address LDS from a per-block smem copy.
// ---------------------------------------------------------------------------
__global__ __launch_bounds__(128, 4)
void gap_main_kernel(const float* __restrict__ X,
                     const int*  __restrict__ rowseg,
                     float* __restrict__ out,
                     int N) {
    __shared__ float sx[16][D_DIM];   // 25.6 KB

    const int tid = threadIdx.x;
    const int w   = tid >> 5;          // warp 0..3
    const int l   = tid & 31;
    const long long row0 = ((long long)blockIdx.x * 4 + w) * 4;

    unsigned long long xl[4][NBB];
    float nrm[4];

    #pragma unroll
    for (int r = 0; r < 4; ++r) {
        long long row = row0 + r;
        bool rv = (row < (long long)N);
        const float2* xr = (const float2*)(X + (size_t)(rv ? row : 0) * D_DIM);
        float nr = 0.f;
        float* srow = sx[w * 4 + r];
        #pragma unroll
        for (int bb = 0; bb < NBB; ++bb) {
            int b = 2 * l + 64 * bb;
            F2U v; v.f = make_float2(0.f, 0.f);
            if (rv && b < D_DIM) v.f = xr[l + 32 * bb];
            xl[r][bb] = v.u;
            nr = fmaf(v.f.x, v.f.x, fmaf(v.f.y, v.f.y, nr));
            if (b < D_DIM) { srow[b] = v.f.x; srow[b + 1] = v.f.y; }
        }
        nrm[r] = nr;
    }
    __syncwarp();

    const float* s0 = sx[w * 4 + 0];
    const float* s1 = sx[w * 4 + 1];
    const float* s2 = sx[w * 4 + 2];
    const float* s3 = sx[w * 4 + 3];

    float v0 = 0.f, v1 = 0.f, v2 = 0.f, v3 = 0.f;

    #pragma unroll 2
    for (int a = 0; a < D_DIM; ++a) {
        const unsigned long long* q =
            (const unsigned long long*)(g_Qp + (size_t)a * QSTRIDE) + l;
        unsigned long long t0 = 0ull, t1 = 0ull, t2 = 0ull, t3 = 0ull;
        #pragma unroll
        for (int bb = 0; bb < NBB; ++bb) {
            unsigned long long qv = q[32 * bb];
            t0 = fma2(qv, xl[0][bb], t0);
            t1 = fma2(qv, xl[1][bb], t1);
            t2 = fma2(qv, xl[2][bb], t2);
            t3 = fma2(qv, xl[3][bb], t3);
        }
        F2U u0, u1, u2, u3;
        u0.u = t0; u1.u = t1; u2.u = t2; u3.u = t3;
        v0 = fmaf(s0[a], u0.f.x + u0.f.y, v0);
        v1 = fmaf(s1[a], u1.f.x + u1.f.y, v1);
        v2 = fmaf(s2[a], u2.f.x + u2.f.y, v2);
        v3 = fmaf(s3[a], u3.f.x + u3.f.y, v3);
    }

    float vl[4] = { v0, v1, v2, v3 };
    #pragma unroll
    for (int r = 0; r < 4; ++r) {
        float v = warp_sum(vl[r]);
        float n = warp_sum(nrm[r]);
        long long row = row0 + r;
        if (l == 0 && row < (long long)N) {
            atomicAdd(out + rowseg[row], v / n);
        }
    }
}

// ---------------------------------------------------------------------------
extern "C" void kernel_launch(void* const* d_in, const int* in_sizes, int n_in,
                              void* d_out, int out_size) {
    const float* X      = (const float*)d_in[0];
    const float* SP     = (const float*)d_in[1];
    const float* W      = (const float*)d_in[2];
    const int*   rowseg = (const int*)  d_in[4];
    const int*   colseg = (const int*)  d_in[5];
    float* out = (float*)d_out;

    const int N = in_sizes[4];   // number of environments
    const int M = in_sizes[5];   // number of support points

    // 1) zero output
    zero_out_kernel<<<(out_size + 255) / 256, 256>>>(out, out_size);

    // 2) build Q (grid covers padded 448 columns x 400 rows in 32x32 tiles)
    dim3 qgrid((QSTRIDE + 31) / 32, (D_DIM + 31) / 32);
    build_q_kernel<<<qgrid, 256>>>(SP, W, colseg, M);

    // 3) fused quadratic-form + segment reduction
    int nblocks = (N + 15) / 16;
    gap_main_kernel<<<nblocks, 128>>>(X, rowseg, out, N);
}

// round 8
// speedup vs baseline: 1.0042x; 1.0042x over previous
#include <cuda_runtime.h>
#include <cstdint>

// ---------------------------------------------------------------------------
// FullGapModel collapse:
//   out[s] = sum_{i: row_seg[i]==s} (x_i^T Q x_i) / ||x_i||^2
//   Q[a,b] = sum_j weights[col_seg[j]] * SP[j,a] * SP[j,b]   (400x400, symmetric)
//
// Inputs (metadata order):
//   0: power_spectrum  f32 [N=100000, D=400]
//   1: support_points  f32 [M=2000,  D=400]
//   2: weights         f32 [1, T=100]
//   3: all_species     i32 [N]          (unused by reference)
//   4: row_seg         i32 [N]          (values in [0, S))
//   5: col_seg         i32 [M]          (values in [0, T))
// Output: f32 [S=2000]
// ---------------------------------------------------------------------------

#define D_DIM   400
#define QSTRIDE 448          // padded row stride; pad columns are zero
#define NBB     7            // float2 chunks per lane: b = 2*lane + 64*bb covers 448

// Scratch for Q (device global — no allocation allowed). 400*448*4 = 716.8 KB.
__device__ float g_Qp[D_DIM * QSTRIDE];

union F2U { float2 f; unsigned long long u; };

// Packed dual-fp32 FMA (sm_103a f32x2 pipe: 2x scalar FFMA throughput).
__device__ __forceinline__ unsigned long long fma2(unsigned long long a,
                                                   unsigned long long b,
                                                   unsigned long long c) {
    unsigned long long d;
    asm("fma.rn.f32x2 %0, %1, %2, %3;" : "=l"(d) : "l"(a), "l"(b), "l"(c));
    return d;
}

__device__ __forceinline__ float warp_sum(float v) {
    #pragma unroll
    for (int o = 16; o > 0; o >>= 1) v += __shfl_xor_sync(0xFFFFFFFFu, v, o);
    return v;
}

// ---------------------------------------------------------------------------
// Zero the output (harness poisons d_out with 0xAA).
// ---------------------------------------------------------------------------
__global__ void zero_out_kernel(float* __restrict__ out, int n) {
    int i = blockIdx.x * blockDim.x + threadIdx.x;
    if (i < n) out[i] = 0.0f;
}

// ---------------------------------------------------------------------------
// Build Q = SP^T * diag(w') * SP, where w'_j = weights[col_seg[j]].
// 32x32 output tile per 256-thread block, 2x2 register blocking per thread.
// Pad columns [400,448) are written as zeros (Bs loads are zero there).
// ---------------------------------------------------------------------------
__global__ __launch_bounds__(256)
void build_q_kernel(const float* __restrict__ SP,
                    const float* __restrict__ W,
                    const int*  __restrict__ colseg,
                    int M) {
    __shared__ float As[32][33];
    __shared__ float Bs[32][33];

    const int a0 = blockIdx.y * 32;       // row tile (a < 400)
    const int b0 = blockIdx.x * 32;       // col tile (b < 448, incl. pad)
    const int tid = threadIdx.x;
    const int ty = tid >> 4;              // 0..15
    const int tx = tid & 15;              // 0..15

    float c00 = 0.f, c01 = 0.f, c10 = 0.f, c11 = 0.f;

    for (int j0 = 0; j0 < M; j0 += 32) {
        // Cooperative load: 1024 elements per array, 4 per thread.
        #pragma unroll
        for (int e = tid; e < 1024; e += 256) {
            int jj  = e >> 5;
            int col = e & 31;
            int j   = j0 + jj;
            float av = 0.f, bv = 0.f;
            if (j < M) {
                float wp = W[colseg[j]];
                int a = a0 + col;
                int b = b0 + col;
                if (a < D_DIM) av = SP[(size_t)j * D_DIM + a] * wp;
                if (b < D_DIM) bv = SP[(size_t)j * D_DIM + b];
            }
            As[jj][col] = av;
            Bs[jj][col] = bv;
        }
        __syncthreads();

        #pragma unroll
        for (int jj = 0; jj < 32; ++jj) {
            float a0r = As[jj][ty];
            float a1r = As[jj][ty + 16];
            float b0r = Bs[jj][tx];
            float b1r = Bs[jj][tx + 16];
            c00 = fmaf(a0r, b0r, c00);
            c01 = fmaf(a0r, b1r, c01);
            c10 = fmaf(a1r, b0r, c10);
            c11 = fmaf(a1r, b1r, c11);
        }
        __syncthreads();
    }

    int a_lo = a0 + ty, a_hi = a0 + ty + 16;
    int b_lo = b0 + tx, b_hi = b0 + tx + 16;
    if (a_lo < D_DIM) {
        if (b_lo < QSTRIDE) g_Qp[(size_t)a_lo * QSTRIDE + b_lo] = c00;
        if (b_hi < QSTRIDE) g_Qp[(size_t)a_lo * QSTRIDE + b_hi] = c01;
    }
    if (a_hi < D_DIM) {
        if (b_lo < QSTRIDE) g_Qp[(size_t)a_hi * QSTRIDE + b_lo] = c10;
        if (b_hi < QSTRIDE) g_Qp[(size_t)a_hi * QSTRIDE + b_hi] = c11;
    }
}

// ---------------------------------------------------------------------------
// Main pass: per row i, v_i = (x^T Q x)/||x||^2; atomicAdd into out[row_seg[i]].
// 128 threads = 4 warps/block, 4 rows/warp, 16 rows/block.
// Per-lane x slices in registers (b = 2*lane + 64*bb), Q rows streamed,
// x_a broadcast via uniform-address LDS from a per-block smem copy.
// ---------------------------------------------------------------------------
__global__ __launch_bounds__(128, 4)
void gap_main_kernel(const float* __restrict__ X,
                     const int*  __restrict__ rowseg,
                     float* __restrict__ out,
                     int N) {
    __shared__ float sx[16][D_DIM];   // 25.6 KB

    const int tid = threadIdx.x;
    const int w   = tid >> 5;          // warp 0..3
    const int l   = tid & 31;
    const long long row0 = ((long long)blockIdx.x * 4 + w) * 4;

    unsigned long long xl[4][NBB];
    float nrm[4];

    #pragma unroll
    for (int r = 0; r < 4; ++r) {
        long long row = row0 + r;
        bool rv = (row < (long long)N);
        const float2* xr = (const float2*)(X + (size_t)(rv ? row : 0) * D_DIM);
        float nr = 0.f;
        float* srow = sx[w * 4 + r];
        #pragma unroll
        for (int bb = 0; bb < NBB; ++bb) {
            int b = 2 * l + 64 * bb;
            F2U v; v.f = make_float2(0.f, 0.f);
            if (rv && b < D_DIM) v.f = xr[l + 32 * bb];
            xl[r][bb] = v.u;
            nr = fmaf(v.f.x, v.f.x, fmaf(v.f.y, v.f.y, nr));
            if (b < D_DIM) { srow[b] = v.f.x; srow[b + 1] = v.f.y; }
        }
        nrm[r] = nr;
    }
    __syncwarp();

    const float* s0 = sx[w * 4 + 0];
    const float* s1 = sx[w * 4 + 1];
    const float* s2 = sx[w * 4 + 2];
    const float* s3 = sx[w * 4 + 3];

    float v0 = 0.f, v1 = 0.f, v2 = 0.f, v3 = 0.f;

    #pragma unroll 2
    for (int a = 0; a < D_DIM; ++a) {
        const unsigned long long* q =
            (const unsigned long long*)(g_Qp + (size_t)a * QSTRIDE) + l;
        unsigned long long t0 = 0ull, t1 = 0ull, t2 = 0ull, t3 = 0ull;
        #pragma unroll
        for (int bb = 0; bb < NBB; ++bb) {
            unsigned long long qv = q[32 * bb];
            t0 = fma2(qv, xl[0][bb], t0);
            t1 = fma2(qv, xl[1][bb], t1);
            t2 = fma2(qv, xl[2][bb], t2);
            t3 = fma2(qv, xl[3][bb], t3);
        }
        F2U u0, u1, u2, u3;
        u0.u = t0; u1.u = t1; u2.u = t2; u3.u = t3;
        v0 = fmaf(s0[a], u0.f.x + u0.f.y, v0);
        v1 = fmaf(s1[a], u1.f.x + u1.f.y, v1);
        v2 = fmaf(s2[a], u2.f.x + u2.f.y, v2);
        v3 = fmaf(s3[a], u3.f.x + u3.f.y, v3);
    }

    float vl[4] = { v0, v1, v2, v3 };
    #pragma unroll
    for (int r = 0; r < 4; ++r) {
        float v = warp_sum(vl[r]);
        float n = warp_sum(nrm[r]);
        long long row = row0 + r;
        if (l == 0 && row < (long long)N) {
            atomicAdd(out + rowseg[row], v / n);
        }
    }
}

// ---------------------------------------------------------------------------
extern "C" void kernel_launch(void* const* d_in, const int* in_sizes, int n_in,
                              void* d_out, int out_size) {
    const float* X      = (const float*)d_in[0];
    const float* SP     = (const float*)d_in[1];
    const float* W      = (const float*)d_in[2];
    const int*   rowseg = (const int*)  d_in[4];
    const int*   colseg = (const int*)  d_in[5];
    float* out = (float*)d_out;

    const int N = in_sizes[4];   // number of environments
    const int M = in_sizes[5];   // number of support points

    // 1) zero output
    zero_out_kernel<<<(out_size + 255) / 256, 256>>>(out, out_size);

    // 2) build Q (grid covers padded 448 columns x 400 rows in 32x32 tiles)
    dim3 qgrid((QSTRIDE + 31) / 32, (D_DIM + 31) / 32);
    build_q_kernel<<<qgrid, 256>>>(SP, W, colseg, M);

    // 3) fused quadratic-form + segment reduction
    int nblocks = (N + 15) / 16;
    gap_main_kernel<<<nblocks, 128>>>(X, rowseg, out, N);
}

// round 10
// speedup vs baseline: 1.1571x; 1.1523x over previous
#include <cuda_runtime.h>
#include <cuda_bf16.h>
#include <cstdint>

// ---------------------------------------------------------------------------
// FullGapModel collapse:
//   out[s] = sum_{i: row_seg[i]==s} (x_i^T Q x_i) / ||x_i||^2
//   Q[a,b] = sum_j weights[col_seg[j]] * SP[j,a] * SP[j,b]   (400x400, sym)
//
// tcgen05 is unavailable (harness PTX target is plain sm_103), so the tensor
// path is classic mma.sync bf16 (HMMA). Precision via 3-product split:
//   D = Xhi*Qhi + Xhi*Qlo + Xlo*Qhi   (error ~ eps_bf16^2)
// then v_i = sum_n x[i,n](fp32 exact) * D[i,n],  nrm_i = ||x_i||^2.
// ---------------------------------------------------------------------------

#define D_DIM    400
#define BM       128
#define BN       64
#define BK       80            // 5 k16-steps per chunk; 400 = 5*80
#define NPADQ    448           // Q padded N rows (7 chunks of 64); rows>=400 zero
#define NCHUNK   7
#define KCHUNKS  5
#define TOTCH    15            // 3 products x 5 K-chunks
#define NROWS_PAD 100096       // 782 * 128  (>= N, multiple of BM)

#define AS_STRIDE 88           // bf16 elems per smem row (80 + 8 pad)
#define A_ELEMS   (BM * AS_STRIDE)            // 11264
#define B_ELEMS   (BN * AS_STRIDE)            // 5632
#define STAGE_B   ((A_ELEMS + B_ELEMS) * 2)   // bytes per stage = 33792
#define SV_OFF    (2 * STAGE_B)               // 67584
#define SN_OFF    (SV_OFF + BM * 4)           // 68096
#define SMEM_TOTAL (SN_OFF + BM * 4)          // 68608

// Static global scratch (no allocation allowed).
__device__ __nv_bfloat16 g_Xhi[(size_t)NROWS_PAD * D_DIM];   // 80.1 MB
__device__ __nv_bfloat16 g_Xlo[(size_t)NROWS_PAD * D_DIM];   // 80.1 MB
__device__ __nv_bfloat16 g_Qhi[NPADQ * D_DIM];               // 358 KB
__device__ __nv_bfloat16 g_Qlo[NPADQ * D_DIM];               // 358 KB

// ---------------- helpers --------------------------------------------------

__device__ __forceinline__ uint32_t smem_u32(const void* p) {
    uint32_t a;
    asm("{ .reg .u64 t; cvta.to.shared.u64 t, %1; cvt.u32.u64 %0, t; }"
        : "=r"(a) : "l"(p));
    return a;
}

__device__ __forceinline__ void ldsm_x4(uint32_t* r, uint32_t addr) {
    asm volatile("ldmatrix.sync.aligned.m8n8.x4.shared.b16 {%0,%1,%2,%3}, [%4];"
                 : "=r"(r[0]), "=r"(r[1]), "=r"(r[2]), "=r"(r[3]) : "r"(addr));
}

__device__ __forceinline__ void mma_bf16(float* c, const uint32_t* a,
                                         uint32_t b0, uint32_t b1) {
    asm volatile(
        "mma.sync.aligned.m16n8k16.row.col.f32.bf16.bf16.f32 "
        "{%0,%1,%2,%3}, {%4,%5,%6,%7}, {%8,%9}, {%0,%1,%2,%3};"
        : "+f"(c[0]), "+f"(c[1]), "+f"(c[2]), "+f"(c[3])
        : "r"(a[0]), "r"(a[1]), "r"(a[2]), "r"(a[3]), "r"(b0), "r"(b1));
}

__device__ __forceinline__ uint32_t pack_bf2(__nv_bfloat16 a, __nv_bfloat16 b) {
    __nv_bfloat162 t = __halves2bfloat162(a, b);
    return *reinterpret_cast<uint32_t*>(&t);
}

// ---------------------------------------------------------------------------
__global__ void zero_out_kernel(float* __restrict__ out, int n) {
    int i = blockIdx.x * blockDim.x + threadIdx.x;
    if (i < n) out[i] = 0.0f;
}

// ---------------------------------------------------------------------------
// Prepass: X fp32 -> (Xhi, Xlo) bf16, rows padded with zeros to NROWS_PAD.
// One float4 (4 elements) per thread.
// ---------------------------------------------------------------------------
__global__ __launch_bounds__(256)
void split_x_kernel(const float* __restrict__ X, int N) {
    size_t idx = (size_t)blockIdx.x * blockDim.x + threadIdx.x;
    const size_t total = (size_t)NROWS_PAD * (D_DIM / 4);
    if (idx >= total) return;
    size_t row = idx / (D_DIM / 4);
    int    c4  = (int)(idx % (D_DIM / 4));
    float4 v = make_float4(0.f, 0.f, 0.f, 0.f);
    if (row < (size_t)N)
        v = reinterpret_cast<const float4*>(X + row * D_DIM)[c4];
    float f[4] = { v.x, v.y, v.z, v.w };
    __nv_bfloat16 h[4], l[4];
    #pragma unroll
    for (int q = 0; q < 4; ++q) {
        h[q] = __float2bfloat16(f[q]);
        l[q] = __float2bfloat16(f[q] - __bfloat162float(h[q]));
    }
    uint2 hv = make_uint2(pack_bf2(h[0], h[1]), pack_bf2(h[2], h[3]));
    uint2 lv = make_uint2(pack_bf2(l[0], l[1]), pack_bf2(l[2], l[3]));
    size_t off = row * D_DIM + (size_t)c4 * 4;
    *reinterpret_cast<uint2*>(g_Xhi + off) = hv;
    *reinterpret_cast<uint2*>(g_Xlo + off) = lv;
}

// ---------------------------------------------------------------------------
// Build Q = SP^T diag(w') SP in split bf16, layout [NPADQ][400], rows>=400 = 0.
// ---------------------------------------------------------------------------
__global__ __launch_bounds__(256)
void build_q_kernel(const float* __restrict__ SP,
                    const float* __restrict__ W,
                    const int*  __restrict__ colseg,
                    int M) {
    __shared__ float As[32][33];
    __shared__ float Bs[32][33];

    const int a0 = blockIdx.y * 32;       // n index (< NPADQ)
    const int b0 = blockIdx.x * 32;       // k index (< 416 grid, store k<400)
    const int tid = threadIdx.x;
    const int ty = tid >> 4;
    const int tx = tid & 15;

    float c00 = 0.f, c01 = 0.f, c10 = 0.f, c11 = 0.f;

    for (int j0 = 0; j0 < M; j0 += 32) {
        #pragma unroll
        for (int e = tid; e < 1024; e += 256) {
            int jj  = e >> 5;
            int col = e & 31;
            int j   = j0 + jj;
            float av = 0.f, bv = 0.f;
            if (j < M) {
                float wp = W[colseg[j]];
                int a = a0 + col;
                int b = b0 + col;
                if (a < D_DIM) av = SP[(size_t)j * D_DIM + a] * wp;
                if (b < D_DIM) bv = SP[(size_t)j * D_DIM + b];
            }
            As[jj][col] = av;
            Bs[jj][col] = bv;
        }
        __syncthreads();

        #pragma unroll
        for (int jj = 0; jj < 32; ++jj) {
            float a0r = As[jj][ty];
            float a1r = As[jj][ty + 16];
            float b0r = Bs[jj][tx];
            float b1r = Bs[jj][tx + 16];
            c00 = fmaf(a0r, b0r, c00);
            c01 = fmaf(a0r, b1r, c01);
            c10 = fmaf(a1r, b0r, c10);
            c11 = fmaf(a1r, b1r, c11);
        }
        __syncthreads();
    }

    float vals[4] = { c00, c01, c10, c11 };
    int   aa[4]   = { a0 + ty, a0 + ty, a0 + ty + 16, a0 + ty + 16 };
    int   bb[4]   = { b0 + tx, b0 + tx + 16, b0 + tx, b0 + tx + 16 };
    #pragma unroll
    for (int q = 0; q < 4; ++q) {
        if (aa[q] < NPADQ && bb[q] < D_DIM) {
            __nv_bfloat16 hi = __float2bfloat16(vals[q]);
            __nv_bfloat16 lo = __float2bfloat16(vals[q] - __bfloat162float(hi));
            size_t idx = (size_t)aa[q] * D_DIM + bb[q];
            g_Qhi[idx] = hi;
            g_Qlo[idx] = lo;
        }
    }
}

// ---------------------------------------------------------------------------
// Main kernel: 256 threads = 8 warps (wm = wid&3 -> 32-row slice,
// wn = wid>>2 -> 32-col slice of the 64-wide N chunk).
// ---------------------------------------------------------------------------
__global__ __launch_bounds__(256, 2)
void gap_mma_kernel(const float* __restrict__ X,
                    const int*  __restrict__ rowseg,
                    float* __restrict__ out,
                    int N) {
    extern __shared__ __align__(16) char smem[];
    __nv_bfloat16* const sA[2] = {
        reinterpret_cast<__nv_bfloat16*>(smem),
        reinterpret_cast<__nv_bfloat16*>(smem + STAGE_B) };
    __nv_bfloat16* const sB[2] = {
        reinterpret_cast<__nv_bfloat16*>(smem) + A_ELEMS,
        reinterpret_cast<__nv_bfloat16*>(smem + STAGE_B) + A_ELEMS };
    float* const sv = reinterpret_cast<float*>(smem + SV_OFF);
    float* const sn = reinterpret_cast<float*>(smem + SN_OFF);

    const int tid  = threadIdx.x;
    const int lane = tid & 31;
    const int wid  = tid >> 5;
    const int wm   = wid & 3;            // row slice 0..3
    const int wn   = wid >> 2;           // col slice 0..1
    const int g    = lane >> 2;          // groupID
    const int tg   = lane & 3;

    const uint32_t sA_u32[2] = { smem_u32(sA[0]), smem_u32(sA[1]) };
    const uint32_t sB_u32[2] = { smem_u32(sB[0]), smem_u32(sB[1]) };

    // ldmatrix per-lane row/col offsets
    const int arow_l = lane & 15;
    const int acol_l = (lane >> 4) * 8;
    const int brow_l = (lane & 7) + ((lane >> 4) << 3);
    const int bcol_l = ((lane >> 3) & 1) * 8;

    const size_t row0 = (size_t)blockIdx.x * BM;

    if (tid < BM) { sv[tid] = 0.f; sn[tid] = 0.f; }

    float vp[4] = { 0.f, 0.f, 0.f, 0.f };
    float np[4] = { 0.f, 0.f, 0.f, 0.f };

    for (int nc = 0; nc < NCHUNK; ++nc) {
        float c[2][4][4];
        #pragma unroll
        for (int mt = 0; mt < 2; ++mt)
            #pragma unroll
            for (int nt = 0; nt < 4; ++nt)
                #pragma unroll
                for (int q = 0; q < 4; ++q) c[mt][nt][q] = 0.f;

        // ---- prologue: stage chunk 0 ----
        {
            const __nv_bfloat16* Asrc = g_Xhi;   // chunk 0: product 0 (hi*hi)
            const __nv_bfloat16* Bsrc = g_Qhi;
            const int ks = 0;
            #pragma unroll
            for (int j = 0; j < 5; ++j) {
                int e = tid + 256 * j;           // 0..1279
                int r = e / 10, cc = e % 10;
                uint4 v = *reinterpret_cast<const uint4*>(
                    Asrc + (row0 + r) * D_DIM + ks + cc * 8);
                *reinterpret_cast<uint4*>(sA[0] + r * AS_STRIDE + cc * 8) = v;
            }
            #pragma unroll
            for (int j = 0; j < 3; ++j) {
                int e = tid + 256 * j;
                if (e < 640) {
                    int r = e / 10, cc = e % 10;
                    uint4 v = *reinterpret_cast<const uint4*>(
                        Bsrc + (size_t)(nc * BN + r) * D_DIM + ks + cc * 8);
                    *reinterpret_cast<uint4*>(sB[0] + r * AS_STRIDE + cc * 8) = v;
                }
            }
        }
        __syncthreads();

        // ---- K pipeline: 15 chunks = 3 products x 5 K-slices ----
        for (int kc = 0; kc < TOTCH; ++kc) {
            const int s = kc & 1;

            // prefetch next chunk into registers
            uint4 ar[5];
            uint4 br[3];
            const bool havenext = (kc + 1 < TOTCH);
            if (havenext) {
                int knext = kc + 1;
                int p  = knext / KCHUNKS;
                int ks = (knext % KCHUNKS) * BK;
                const __nv_bfloat16* Asrc = (p == 2) ? g_Xlo : g_Xhi;
                const __nv_bfloat16* Bsrc = (p == 1) ? g_Qlo : g_Qhi;
                #pragma unroll
                for (int j = 0; j < 5; ++j) {
                    int e = tid + 256 * j;
                    int r = e / 10, cc = e % 10;
                    ar[j] = *reinterpret_cast<const uint4*>(
                        Asrc + (row0 + r) * D_DIM + ks + cc * 8);
                }
                #pragma unroll
                for (int j = 0; j < 3; ++j) {
                    int e = tid + 256 * j;
                    if (e < 640) {
                        int r = e / 10, cc = e % 10;
                        br[j] = *reinterpret_cast<const uint4*>(
                            Bsrc + (size_t)(nc * BN + r) * D_DIM + ks + cc * 8);
                    }
                }
            }

            // compute current chunk
            #pragma unroll
            for (int kk = 0; kk < 5; ++kk) {
                uint32_t a[2][4], b[2][4];
                #pragma unroll
                for (int mt = 0; mt < 2; ++mt) {
                    uint32_t addr = sA_u32[s] +
                        (uint32_t)(((wm * 32 + 16 * mt + arow_l) * AS_STRIDE
                                    + kk * 16 + acol_l) * 2);
                    ldsm_x4(a[mt], addr);
                }
                #pragma unroll
                for (int nh = 0; nh < 2; ++nh) {
                    uint32_t addr = sB_u32[s] +
                        (uint32_t)(((wn * 32 + 16 * nh + brow_l) * AS_STRIDE
                                    + kk * 16 + bcol_l) * 2);
                    ldsm_x4(b[nh], addr);
                }
                #pragma unroll
                for (int mt = 0; mt < 2; ++mt)
                    #pragma unroll
                    for (int nt = 0; nt < 4; ++nt)
                        mma_bf16(c[mt][nt], a[mt],
                                 b[nt >> 1][(nt & 1) * 2],
                                 b[nt >> 1][(nt & 1) * 2 + 1]);
            }

            // stage next chunk
            if (havenext) {
                const int sn2 = (kc + 1) & 1;
                #pragma unroll
                for (int j = 0; j < 5; ++j) {
                    int e = tid + 256 * j;
                    int r = e / 10, cc = e % 10;
                    *reinterpret_cast<uint4*>(sA[sn2] + r * AS_STRIDE + cc * 8) = ar[j];
                }
                #pragma unroll
                for (int j = 0; j < 3; ++j) {
                    int e = tid + 256 * j;
                    if (e < 640) {
                        int r = e / 10, cc = e % 10;
                        *reinterpret_cast<uint4*>(sB[sn2] + r * AS_STRIDE + cc * 8) = br[j];
                    }
                }
            }
            __syncthreads();
        }

        // ---- fold this N chunk: v += x.D, nrm += x.x  (exact fp32 x) ----
        #pragma unroll
        for (int mt = 0; mt < 2; ++mt) {
            const int    r0l = wm * 32 + 16 * mt + g;
            const size_t R0  = row0 + (size_t)r0l;
            #pragma unroll
            for (int nt = 0; nt < 4; ++nt) {
                int C0 = nc * 64 + wn * 32 + 8 * nt + 2 * tg;
                if (C0 < D_DIM) {
                    if (R0 < (size_t)N) {
                        float2 x0 = __ldg(reinterpret_cast<const float2*>(
                            X + R0 * D_DIM + C0));
                        vp[2 * mt] = fmaf(x0.x, c[mt][nt][0],
                                      fmaf(x0.y, c[mt][nt][1], vp[2 * mt]));
                        np[2 * mt] = fmaf(x0.x, x0.x,
                                      fmaf(x0.y, x0.y, np[2 * mt]));
                    }
                    if (R0 + 8 < (size_t)N) {
                        float2 x1 = __ldg(reinterpret_cast<const float2*>(
                            X + (R0 + 8) * D_DIM + C0));
                        vp[2 * mt + 1] = fmaf(x1.x, c[mt][nt][2],
                                          fmaf(x1.y, c[mt][nt][3], vp[2 * mt + 1]));
                        np[2 * mt + 1] = fmaf(x1.x, x1.x,
                                          fmaf(x1.y, x1.y, np[2 * mt + 1]));
                    }
                }
            }
        }
    }

    // reduce across the 4 lanes sharing each row (tg), then smem-accumulate
    #pragma unroll
    for (int i = 0; i < 4; ++i) {
        vp[i] += __shfl_xor_sync(0xFFFFFFFFu, vp[i], 1);
        vp[i] += __shfl_xor_sync(0xFFFFFFFFu, vp[i], 2);
        np[i] += __shfl_xor_sync(0xFFFFFFFFu, np[i], 1);
        np[i] += __shfl_xor_sync(0xFFFFFFFFu, np[i], 2);
    }
    if (tg == 0) {
        #pragma unroll
        for (int i = 0; i < 4; ++i) {
            int mt = i >> 1, hi = i & 1;
            int r  = wm * 32 + 16 * mt + 8 * hi + g;
            atomicAdd(&sv[r], vp[i]);
            atomicAdd(&sn[r], np[i]);
        }
    }
    __syncthreads();

    // final: one atomic per valid row into the segment output
    if (tid < BM) {
        size_t row = row0 + (size_t)tid;
        if (row < (size_t)N) {
            float nr = sn[tid];
            if (nr > 0.f)
                atomicAdd(out + __ldg(rowseg + row), sv[tid] / nr);
        }
    }
}

// ---------------------------------------------------------------------------
extern "C" void kernel_launch(void* const* d_in, const int* in_sizes, int n_in,
                              void* d_out, int out_size) {
    const float* X      = (const float*)d_in[0];
    const float* SP     = (const float*)d_in[1];
    const float* W      = (const float*)d_in[2];
    const int*   rowseg = (const int*)  d_in[4];
    const int*   colseg = (const int*)  d_in[5];
    float* out = (float*)d_out;

    const int N = in_sizes[4];   // environments
    const int M = in_sizes[5];   // support points

    zero_out_kernel<<<(out_size + 255) / 256, 256>>>(out, out_size);

    // prepass: split X into bf16 hi/lo (padded rows zero-filled)
    {
        size_t total = (size_t)NROWS_PAD * (D_DIM / 4);
        int blocks = (int)((total + 255) / 256);
        split_x_kernel<<<blocks, 256>>>(X, N);
    }

    // build split-bf16 Q
    {
        dim3 qgrid((D_DIM + 31) / 32, NPADQ / 32);   // 13 x 14
        build_q_kernel<<<qgrid, 256>>>(SP, W, colseg, M);
    }

    // main fused GEMM + quadratic form + segment reduction
    cudaFuncSetAttribute(gap_mma_kernel,
                         cudaFuncAttributeMaxDynamicSharedMemorySize, SMEM_TOTAL);
    int ntiles = (N + BM - 1) / BM;
    gap_mma_kernel<<<ntiles, 256, SMEM_TOTAL>>>(X, rowseg, out, N);
}

// round 11
// speedup vs baseline: 1.5229x; 1.3161x over previous
#include <cuda_runtime.h>
#include <cuda_bf16.h>
#include <cstdint>

// ---------------------------------------------------------------------------
// FullGapModel collapse:
//   out[s] = sum_{i: row_seg[i]==s} (x_i^T Q x_i) / ||x_i||^2
//   Q[a,b] = sum_j weights[col_seg[j]] * SP[j,a] * SP[j,b]   (400x400, sym)
//
// HMMA bf16 (mma.sync m16n8k16) with 3-product split precision:
//   D = Xhi*Qhi + Xlo*Qhi + Xhi*Qlo     (error ~ eps_bf16^2)
// All 3 products accumulate into the SAME register fragment, so one staging
// of (Ahi, Alo, Bhi, Blo) per 32-wide K slice feeds 24 HMMA per 8 ldmatrix.
// Staging uses cp.async.cg (no LDG->reg->STS round trip).
// ---------------------------------------------------------------------------

#define D_DIM     400
#define KPADX     416          // K padded: 13 slices of 32
#define NSLICE    13
#define NPADQ     448          // Q rows padded: 7 chunks of 64
#define NCHUNK    7
#define BM        128
#define BN        64
#define NROWS_PAD 100096       // 782 * 128

#define AS_ST     40                       // bf16 elems per smem row (32+8 pad)
#define A_EL      (BM * AS_ST)             // 5120
#define B_EL      (BN * AS_ST)             // 2560
#define O_AHI     0
#define O_ALO     A_EL
#define O_BHI     (2 * A_EL)
#define O_BLO     (2 * A_EL + B_EL)
#define STAGE_EL  (2 * A_EL + 2 * B_EL)    // 15360 elems = 30720 B
#define SV_OFF    (2 * STAGE_EL * 2)       // bytes: 61440
#define SN_OFF    (SV_OFF + BM * 4)
#define SMEM_TOTAL (SN_OFF + BM * 4)       // 62464 B

// Static global scratch (no allocation allowed).
__device__ __align__(128) __nv_bfloat16 g_Xhi[(size_t)NROWS_PAD * KPADX];
__device__ __align__(128) __nv_bfloat16 g_Xlo[(size_t)NROWS_PAD * KPADX];
__device__ __align__(128) __nv_bfloat16 g_Qhi[(size_t)NPADQ * KPADX];
__device__ __align__(128) __nv_bfloat16 g_Qlo[(size_t)NPADQ * KPADX];

// ---------------- helpers --------------------------------------------------

__device__ __forceinline__ uint32_t smem_u32(const void* p) {
    uint32_t a;
    asm("{ .reg .u64 t; cvta.to.shared.u64 t, %1; cvt.u32.u64 %0, t; }"
        : "=r"(a) : "l"(p));
    return a;
}

__device__ __forceinline__ void cp16(uint32_t dst, const void* src) {
    asm volatile("cp.async.cg.shared.global [%0], [%1], 16;"
                 :: "r"(dst), "l"(src) : "memory");
}
__device__ __forceinline__ void cp_commit() {
    asm volatile("cp.async.commit_group;" ::: "memory");
}
template <int N>
__device__ __forceinline__ void cp_wait() {
    asm volatile("cp.async.wait_group %0;" :: "n"(N) : "memory");
}

__device__ __forceinline__ void ldsm_x4(uint32_t* r, uint32_t addr) {
    asm volatile("ldmatrix.sync.aligned.m8n8.x4.shared.b16 {%0,%1,%2,%3}, [%4];"
                 : "=r"(r[0]), "=r"(r[1]), "=r"(r[2]), "=r"(r[3]) : "r"(addr));
}

__device__ __forceinline__ void mma_bf16(float* c, const uint32_t* a,
                                         uint32_t b0, uint32_t b1) {
    asm volatile(
        "mma.sync.aligned.m16n8k16.row.col.f32.bf16.bf16.f32 "
        "{%0,%1,%2,%3}, {%4,%5,%6,%7}, {%8,%9}, {%0,%1,%2,%3};"
        : "+f"(c[0]), "+f"(c[1]), "+f"(c[2]), "+f"(c[3])
        : "r"(a[0]), "r"(a[1]), "r"(a[2]), "r"(a[3]), "r"(b0), "r"(b1));
}

__device__ __forceinline__ uint32_t pack_bf2(__nv_bfloat16 a, __nv_bfloat16 b) {
    __nv_bfloat162 t = __halves2bfloat162(a, b);
    return *reinterpret_cast<uint32_t*>(&t);
}

// ---------------------------------------------------------------------------
__global__ void zero_out_kernel(float* __restrict__ out, int n) {
    int i = blockIdx.x * blockDim.x + threadIdx.x;
    if (i < n) out[i] = 0.0f;
}

// ---------------------------------------------------------------------------
// Prepass: X fp32 -> (Xhi, Xlo) bf16 with K padded to 416, rows to NROWS_PAD.
// One 16B output chunk (8 bf16) per thread per array.
// ---------------------------------------------------------------------------
__global__ __launch_bounds__(256)
void split_x_kernel(const float* __restrict__ X, int N) {
    size_t idx = (size_t)blockIdx.x * blockDim.x + threadIdx.x;
    const size_t total = (size_t)NROWS_PAD * (KPADX / 8);
    if (idx >= total) return;
    size_t row = idx / (KPADX / 8);
    int    c8  = (int)(idx % (KPADX / 8));      // 0..51
    uint4 hv = make_uint4(0u, 0u, 0u, 0u);
    uint4 lv = make_uint4(0u, 0u, 0u, 0u);
    if (row < (size_t)N && c8 < (D_DIM / 8)) {
        const float4* p = reinterpret_cast<const float4*>(X + row * D_DIM + c8 * 8);
        float4 v0 = p[0], v1 = p[1];
        float f[8] = { v0.x, v0.y, v0.z, v0.w, v1.x, v1.y, v1.z, v1.w };
        __nv_bfloat16 h[8], l[8];
        #pragma unroll
        for (int q = 0; q < 8; ++q) {
            h[q] = __float2bfloat16(f[q]);
            l[q] = __float2bfloat16(f[q] - __bfloat162float(h[q]));
        }
        hv = make_uint4(pack_bf2(h[0], h[1]), pack_bf2(h[2], h[3]),
                        pack_bf2(h[4], h[5]), pack_bf2(h[6], h[7]));
        lv = make_uint4(pack_bf2(l[0], l[1]), pack_bf2(l[2], l[3]),
                        pack_bf2(l[4], l[5]), pack_bf2(l[6], l[7]));
    }
    size_t off = row * KPADX + (size_t)c8 * 8;
    *reinterpret_cast<uint4*>(g_Xhi + off) = hv;
    *reinterpret_cast<uint4*>(g_Xlo + off) = lv;
}

// ---------------------------------------------------------------------------
// Build Q = SP^T diag(w') SP in split bf16, layout [NPADQ][KPADX], pads zero.
// ---------------------------------------------------------------------------
__global__ __launch_bounds__(256)
void build_q_kernel(const float* __restrict__ SP,
                    const float* __restrict__ W,
                    const int*  __restrict__ colseg,
                    int M) {
    __shared__ float As[32][33];
    __shared__ float Bs[32][33];

    const int a0 = blockIdx.y * 32;       // n index (< NPADQ)
    const int b0 = blockIdx.x * 32;       // k index (< KPADX)
    const int tid = threadIdx.x;
    const int ty = tid >> 4;
    const int tx = tid & 15;

    float c00 = 0.f, c01 = 0.f, c10 = 0.f, c11 = 0.f;

    for (int j0 = 0; j0 < M; j0 += 32) {
        #pragma unroll
        for (int e = tid; e < 1024; e += 256) {
            int jj  = e >> 5;
            int col = e & 31;
            int j   = j0 + jj;
            float av = 0.f, bv = 0.f;
            if (j < M) {
                float wp = W[colseg[j]];
                int a = a0 + col;
                int b = b0 + col;
                if (a < D_DIM) av = SP[(size_t)j * D_DIM + a] * wp;
                if (b < D_DIM) bv = SP[(size_t)j * D_DIM + b];
            }
            As[jj][col] = av;
            Bs[jj][col] = bv;
        }
        __syncthreads();

        #pragma unroll
        for (int jj = 0; jj < 32; ++jj) {
            float a0r = As[jj][ty];
            float a1r = As[jj][ty + 16];
            float b0r = Bs[jj][tx];
            float b1r = Bs[jj][tx + 16];
            c00 = fmaf(a0r, b0r, c00);
            c01 = fmaf(a0r, b1r, c01);
            c10 = fmaf(a1r, b0r, c10);
            c11 = fmaf(a1r, b1r, c11);
        }
        __syncthreads();
    }

    float vals[4] = { c00, c01, c10, c11 };
    int   aa[4]   = { a0 + ty, a0 + ty, a0 + ty + 16, a0 + ty + 16 };
    int   bb[4]   = { b0 + tx, b0 + tx + 16, b0 + tx, b0 + tx + 16 };
    #pragma unroll
    for (int q = 0; q < 4; ++q) {
        if (aa[q] < NPADQ && bb[q] < KPADX) {
            __nv_bfloat16 hi = __float2bfloat16(vals[q]);
            __nv_bfloat16 lo = __float2bfloat16(vals[q] - __bfloat162float(hi));
            size_t idx = (size_t)aa[q] * KPADX + bb[q];
            g_Qhi[idx] = hi;
            g_Qlo[idx] = lo;
        }
    }
}

// ---------------------------------------------------------------------------
// Main kernel: 256 threads (8 warps: 4 M-slices x 2 N-slices).
// Per N chunk (64 cols): 13 K-slices of 32, cp.async double-buffered,
// each slice staged once feeds all 3 split products (24 HMMA / 8 LDSM / kk).
// ---------------------------------------------------------------------------
__global__ __launch_bounds__(256, 2)
void gap_mma_kernel(const float* __restrict__ X,
                    const int*  __restrict__ rowseg,
                    float* __restrict__ out,
                    int N) {
    extern __shared__ __align__(16) char smem[];
    __nv_bfloat16* const stg0 = reinterpret_cast<__nv_bfloat16*>(smem);
    float* const sv = reinterpret_cast<float*>(smem + SV_OFF);
    float* const sn = reinterpret_cast<float*>(smem + SN_OFF);

    const int tid  = threadIdx.x;
    const int lane = tid & 31;
    const int wid  = tid >> 5;
    const int wm   = wid & 3;            // M slice 0..3 (32 rows)
    const int wn   = wid >> 2;           // N slice 0..1 (32 cols)
    const int g    = lane >> 2;
    const int tg   = lane & 3;

    const uint32_t s_u32 = smem_u32(stg0);

    // ldmatrix per-lane offsets
    const int arow_l = lane & 15;
    const int acol_l = (lane >> 4) * 8;
    const int brow_l = (lane & 7) + ((lane >> 4) << 3);
    const int bcol_l = ((lane >> 3) & 1) * 8;

    const size_t row0 = (size_t)blockIdx.x * BM;

    if (tid < BM) { sv[tid] = 0.f; sn[tid] = 0.f; }

    float vp[4] = { 0.f, 0.f, 0.f, 0.f };
    float np[4] = { 0.f, 0.f, 0.f, 0.f };

    // Per-thread cp.async mapping (6 x 16B per slice):
    //   j=0,1: Ahi rows; j=2,3: Alo rows; j=4: Bhi; j=5: Blo
    const int ra  = tid >> 2;            // for A when j even: rows tid>>2 (+64)
    const int ca  = tid & 3;
    const int rb  = tid >> 2;            // B rows 0..63
    const int cb  = tid & 3;

    for (int nc = 0; nc < NCHUNK; ++nc) {
        float c[2][4][4];
        #pragma unroll
        for (int mt = 0; mt < 2; ++mt)
            #pragma unroll
            for (int nt = 0; nt < 4; ++nt)
                #pragma unroll
                for (int q = 0; q < 4; ++q) c[mt][nt][q] = 0.f;

        const __nv_bfloat16* Bhi_base = g_Qhi + (size_t)(nc * BN) * KPADX;
        const __nv_bfloat16* Blo_base = g_Qlo + (size_t)(nc * BN) * KPADX;

        // ---- stage slice 0 into buffer 0 ----
        {
            const int ks = 0;
            uint32_t sb = s_u32;
            cp16(sb + (O_AHI + (ra      ) * AS_ST + ca * 8) * 2,
                 g_Xhi + (row0 + ra) * KPADX + ks + ca * 8);
            cp16(sb + (O_AHI + (ra + 64 ) * AS_ST + ca * 8) * 2,
                 g_Xhi + (row0 + ra + 64) * KPADX + ks + ca * 8);
            cp16(sb + (O_ALO + (ra      ) * AS_ST + ca * 8) * 2,
                 g_Xlo + (row0 + ra) * KPADX + ks + ca * 8);
            cp16(sb + (O_ALO + (ra + 64 ) * AS_ST + ca * 8) * 2,
                 g_Xlo + (row0 + ra + 64) * KPADX + ks + ca * 8);
            cp16(sb + (O_BHI + rb * AS_ST + cb * 8) * 2,
                 Bhi_base + (size_t)rb * KPADX + ks + cb * 8);
            cp16(sb + (O_BLO + rb * AS_ST + cb * 8) * 2,
                 Blo_base + (size_t)rb * KPADX + ks + cb * 8);
            cp_commit();
        }

        for (int sl = 0; sl < NSLICE; ++sl) {
            // stage next slice into the other buffer
            if (sl + 1 < NSLICE) {
                const int ks = (sl + 1) * 32;
                uint32_t sb = s_u32 + ((sl + 1) & 1) * STAGE_EL * 2;
                cp16(sb + (O_AHI + (ra      ) * AS_ST + ca * 8) * 2,
                     g_Xhi + (row0 + ra) * KPADX + ks + ca * 8);
                cp16(sb + (O_AHI + (ra + 64 ) * AS_ST + ca * 8) * 2,
                     g_Xhi + (row0 + ra + 64) * KPADX + ks + ca * 8);
                cp16(sb + (O_ALO + (ra      ) * AS_ST + ca * 8) * 2,
                     g_Xlo + (row0 + ra) * KPADX + ks + ca * 8);
                cp16(sb + (O_ALO + (ra + 64 ) * AS_ST + ca * 8) * 2,
                     g_Xlo + (row0 + ra + 64) * KPADX + ks + ca * 8);
                cp16(sb + (O_BHI + rb * AS_ST + cb * 8) * 2,
                     Bhi_base + (size_t)rb * KPADX + ks + cb * 8);
                cp16(sb + (O_BLO + rb * AS_ST + cb * 8) * 2,
                     Blo_base + (size_t)rb * KPADX + ks + cb * 8);
                cp_commit();
                cp_wait<1>();
            } else {
                cp_wait<0>();
            }
            __syncthreads();

            // compute on buffer sl&1
            const uint32_t sb = s_u32 + (sl & 1) * STAGE_EL * 2;
            #pragma unroll
            for (int kk = 0; kk < 2; ++kk) {
                uint32_t ahi[2][4], alo[2][4], bhi[2][4], blo[2][4];
                #pragma unroll
                for (int mt = 0; mt < 2; ++mt) {
                    uint32_t ao = (uint32_t)(((wm * 32 + 16 * mt + arow_l) * AS_ST
                                              + kk * 16 + acol_l) * 2);
                    ldsm_x4(ahi[mt], sb + O_AHI * 2 + ao);
                    ldsm_x4(alo[mt], sb + O_ALO * 2 + ao);
                }
                #pragma unroll
                for (int nh = 0; nh < 2; ++nh) {
                    uint32_t bo = (uint32_t)(((wn * 32 + 16 * nh + brow_l) * AS_ST
                                              + kk * 16 + bcol_l) * 2);
                    ldsm_x4(bhi[nh], sb + O_BHI * 2 + bo);
                    ldsm_x4(blo[nh], sb + O_BLO * 2 + bo);
                }
                #pragma unroll
                for (int mt = 0; mt < 2; ++mt)
                    #pragma unroll
                    for (int nt = 0; nt < 4; ++nt) {
                        uint32_t bh0 = bhi[nt >> 1][(nt & 1) * 2];
                        uint32_t bh1 = bhi[nt >> 1][(nt & 1) * 2 + 1];
                        uint32_t bl0 = blo[nt >> 1][(nt & 1) * 2];
                        uint32_t bl1 = blo[nt >> 1][(nt & 1) * 2 + 1];
                        mma_bf16(c[mt][nt], ahi[mt], bh0, bh1);
                        mma_bf16(c[mt][nt], alo[mt], bh0, bh1);
                        mma_bf16(c[mt][nt], ahi[mt], bl0, bl1);
                    }
            }
            __syncthreads();
        }

        // ---- fold this N chunk: v += x.D, nrm += x.x (exact fp32 x) ----
        #pragma unroll
        for (int mt = 0; mt < 2; ++mt) {
            const int    r0l = wm * 32 + 16 * mt + g;
            const size_t R0  = row0 + (size_t)r0l;
            #pragma unroll
            for (int nt = 0; nt < 4; ++nt) {
                int C0 = nc * 64 + wn * 32 + 8 * nt + 2 * tg;
                if (C0 < D_DIM) {
                    if (R0 < (size_t)N) {
                        float2 x0 = __ldg(reinterpret_cast<const float2*>(
                            X + R0 * D_DIM + C0));
                        vp[2 * mt] = fmaf(x0.x, c[mt][nt][0],
                                      fmaf(x0.y, c[mt][nt][1], vp[2 * mt]));
                        np[2 * mt] = fmaf(x0.x, x0.x,
                                      fmaf(x0.y, x0.y, np[2 * mt]));
                    }
                    if (R0 + 8 < (size_t)N) {
                        float2 x1 = __ldg(reinterpret_cast<const float2*>(
                            X + (R0 + 8) * D_DIM + C0));
                        vp[2 * mt + 1] = fmaf(x1.x, c[mt][nt][2],
                                          fmaf(x1.y, c[mt][nt][3], vp[2 * mt + 1]));
                        np[2 * mt + 1] = fmaf(x1.x, x1.x,
                                          fmaf(x1.y, x1.y, np[2 * mt + 1]));
                    }
                }
            }
        }
    }

    // reduce across the 4 lanes sharing each row, then smem accumulate
    #pragma unroll
    for (int i = 0; i < 4; ++i) {
        vp[i] += __shfl_xor_sync(0xFFFFFFFFu, vp[i], 1);
        vp[i] += __shfl_xor_sync(0xFFFFFFFFu, vp[i], 2);
        np[i] += __shfl_xor_sync(0xFFFFFFFFu, np[i], 1);
        np[i] += __shfl_xor_sync(0xFFFFFFFFu, np[i], 2);
    }
    if (tg == 0) {
        #pragma unroll
        for (int i = 0; i < 4; ++i) {
            int mt = i >> 1, hi = i & 1;
            int r  = wm * 32 + 16 * mt + 8 * hi + g;
            atomicAdd(&sv[r], vp[i]);
            atomicAdd(&sn[r], np[i]);
        }
    }
    __syncthreads();

    // one atomic per valid row into the segment output
    if (tid < BM) {
        size_t row = row0 + (size_t)tid;
        if (row < (size_t)N) {
            float nr = sn[tid];
            if (nr > 0.f)
                atomicAdd(out + __ldg(rowseg + row), sv[tid] / nr);
        }
    }
}

// ---------------------------------------------------------------------------
extern "C" void kernel_launch(void* const* d_in, const int* in_sizes, int n_in,
                              void* d_out, int out_size) {
    const float* X      = (const float*)d_in[0];
    const float* SP     = (const float*)d_in[1];
    const float* W      = (const float*)d_in[2];
    const int*   rowseg = (const int*)  d_in[4];
    const int*   colseg = (const int*)  d_in[5];
    float* out = (float*)d_out;

    const int N = in_sizes[4];   // environments
    const int M = in_sizes[5];   // support points

    zero_out_kernel<<<(out_size + 255) / 256, 256>>>(out, out_size);

    // prepass: split X into bf16 hi/lo (K padded to 416, rows to NROWS_PAD)
    {
        size_t total = (size_t)NROWS_PAD * (KPADX / 8);
        int blocks = (int)((total + 255) / 256);
        split_x_kernel<<<blocks, 256>>>(X, N);
    }

    // build split-bf16 Q
    {
        dim3 qgrid(KPADX / 32, NPADQ / 32);   // 13 x 14
        build_q_kernel<<<qgrid, 256>>>(SP, W, colseg, M);
    }

    // main fused GEMM + quadratic form + segment reduction
    cudaFuncSetAttribute(gap_mma_kernel,
                         cudaFuncAttributeMaxDynamicSharedMemorySize, SMEM_TOTAL);
    int ntiles = (N + BM - 1) / BM;
    gap_mma_kernel<<<ntiles, 256, SMEM_TOTAL>>>(X, rowseg, out, N);
}